// round 4
// baseline (speedup 1.0000x reference)
#include <cuda_runtime.h>

// Problem constants (fixed by the dataset)
#define NUM_NODES 20000
#define NUM_EDGES 65536
#define WIDTH     64
#define EDGE_FEAT 6
#define HIDDEN    128

// Scratch (allocation-free rule: __device__ globals)
__device__ float g_h [(size_t)NUM_EDGES * HIDDEN];                 // 33.5 MB  relu(ea@W1+b1)
__device__ float g_g [(size_t)NUM_NODES * HIDDEN * WIDTH];         // 655 MB   g[n][k][v]
__device__ float g_xb[(size_t)NUM_NODES * WIDTH];                  // 5.1 MB   xb[n][v]

// ---------------------------------------------------------------------------
// Zero the output (harness poisons it with 0xAA)
// ---------------------------------------------------------------------------
__global__ void k_zero(float* __restrict__ out, int n) {
    int i = blockIdx.x * blockDim.x + threadIdx.x;
    if (i < n) out[i] = 0.f;
}

// ---------------------------------------------------------------------------
// h[e][k] = relu( sum_f edge_attr[e][f] * W1[f][k] + b1[k] )
// One thread per (e,k) output; 6 MACs each.
// ---------------------------------------------------------------------------
__global__ void k_hidden(const float* __restrict__ ea,
                         const float* __restrict__ W1,
                         const float* __restrict__ b1) {
    int idx = blockIdx.x * blockDim.x + threadIdx.x;   // over E*HIDDEN
    if (idx >= NUM_EDGES * HIDDEN) return;
    int e = idx >> 7;          // idx / 128
    int j = idx & (HIDDEN - 1);
    const float* a = ea + (size_t)e * EDGE_FEAT;
    float s = __ldg(b1 + j);
    #pragma unroll
    for (int f = 0; f < EDGE_FEAT; f++)
        s = fmaf(__ldg(a + f), __ldg(W1 + f * HIDDEN + j), s);
    g_h[idx] = fmaxf(s, 0.f);
}

// ---------------------------------------------------------------------------
// g[n][k][v] = sum_w x[n][w] * W2[k*4096 + w*64 + v]      (blockIdx.y = k < 128)
// xb[n][v]   = sum_w x[n][w] * b2[w*64 + v]               (blockIdx.y == 128)
//
// Tile: 128 nodes x 64 v per CTA, K(=w)=64 depth. 256 threads, 8x4 microtile.
// Smem: Xt[w][n] (transposed, 32KB) + Ws[w][v] (16KB) = 48KB.
// ---------------------------------------------------------------------------
#define GT_N 128
__global__ __launch_bounds__(256) void k_gmat(const float* __restrict__ x,
                                              const float* __restrict__ W2,
                                              const float* __restrict__ b2) {
    __shared__ float Xt[WIDTH][GT_N];    // [w][node-in-tile]
    __shared__ float Ws[WIDTH][WIDTH];   // [w][v], flat == src layout

    const int k  = blockIdx.y;           // 0..127 = W2 row, 128 = bias
    const int n0 = blockIdx.x * GT_N;
    const int t  = threadIdx.x;          // 0..255

    // --- Stage Ws: one row of W2 (4096 floats) or b2 ---
    {
        const float* src = (k < HIDDEN) ? (W2 + (size_t)k * (WIDTH * WIDTH)) : b2;
        const float4* s4 = (const float4*)src;
        float4* d4 = (float4*)&Ws[0][0];
        #pragma unroll
        for (int i = 0; i < (WIDTH * WIDTH / 4) / 256 * 256; i += 256)
            ; // (loop below covers all; this line intentionally no-op)
        for (int i = t; i < WIDTH * WIDTH / 4; i += 256)
            d4[i] = s4[i];
    }

    // --- Stage Xt (transposed): each thread loads half a node row ---
    {
        int n    = t & (GT_N - 1);       // node within tile
        int half = t >> 7;               // which 32-w half
        int gn   = n0 + n;
        #pragma unroll
        for (int q = 0; q < 8; q++) {
            int w = half * 32 + q * 4;
            float4 v4 = make_float4(0.f, 0.f, 0.f, 0.f);
            if (gn < NUM_NODES)
                v4 = *(const float4*)(x + (size_t)gn * WIDTH + w);
            Xt[w + 0][n] = v4.x; Xt[w + 1][n] = v4.y;
            Xt[w + 2][n] = v4.z; Xt[w + 3][n] = v4.w;
        }
    }
    __syncthreads();

    const int tx = t & 15;               // v-group: v = tx*4 .. +3
    const int ty = t >> 4;               // node-group: n = ty*8 .. +7

    float acc[8][4];
    #pragma unroll
    for (int i = 0; i < 8; i++)
        #pragma unroll
        for (int j = 0; j < 4; j++) acc[i][j] = 0.f;

    #pragma unroll 4
    for (int w = 0; w < WIDTH; w++) {
        float4 a0 = *(const float4*)&Xt[w][ty * 8];
        float4 a1 = *(const float4*)&Xt[w][ty * 8 + 4];
        float4 b  = *(const float4*)&Ws[w][tx * 4];
        float av[8] = {a0.x, a0.y, a0.z, a0.w, a1.x, a1.y, a1.z, a1.w};
        float bv[4] = {b.x, b.y, b.z, b.w};
        #pragma unroll
        for (int i = 0; i < 8; i++)
            #pragma unroll
            for (int j = 0; j < 4; j++)
                acc[i][j] = fmaf(av[i], bv[j], acc[i][j]);
    }

    // --- Store ---
    #pragma unroll
    for (int i = 0; i < 8; i++) {
        int n = n0 + ty * 8 + i;
        if (n >= NUM_NODES) break;       // nodes contiguous -> break is safe
        float4 r = make_float4(acc[i][0], acc[i][1], acc[i][2], acc[i][3]);
        if (k < HIDDEN)
            *(float4*)(g_g + ((size_t)n * HIDDEN + k) * WIDTH + tx * 4) = r;
        else
            *(float4*)(g_xb + (size_t)n * WIDTH + tx * 4) = r;
    }
}

// ---------------------------------------------------------------------------
// Per edge e: msg[v] = sum_k h[e][k] * g[s][k][v] + xb[s][v];
// atomicAdd into out[r][v].  Warp per edge; lane owns v = {2*lane, 2*lane+1}.
// h[e][k] is warp-uniform -> warp-coherently skip k where relu output is 0
// (~50% of g gather traffic eliminated).
// ---------------------------------------------------------------------------
__global__ __launch_bounds__(256) void k_msg(const int* __restrict__ senders,
                                             const int* __restrict__ receivers,
                                             float* __restrict__ out) {
    __shared__ float hs[8][HIDDEN];
    const int wi   = threadIdx.x >> 5;
    const int lane = threadIdx.x & 31;
    const int e    = blockIdx.x * 8 + wi;
    if (e >= NUM_EDGES) return;

    // stage this edge's h row into smem (warp-private slab)
    #pragma unroll
    for (int j = 0; j < HIDDEN / 32; j++)
        hs[wi][j * 32 + lane] = g_h[(size_t)e * HIDDEN + j * 32 + lane];
    __syncwarp();

    const int s = senders[e];
    const int r = receivers[e];

    const float2* gp = (const float2*)(g_g + (size_t)s * HIDDEN * WIDTH) + lane;
    float2 acc = ((const float2*)(g_xb + (size_t)s * WIDTH))[lane];

    #pragma unroll 8
    for (int k = 0; k < HIDDEN; k++) {
        float hk = hs[wi][k];            // warp-uniform
        if (hk != 0.f) {
            float2 gv = gp[k * 32];      // 256B coalesced row segment
            acc.x = fmaf(hk, gv.x, acc.x);
            acc.y = fmaf(hk, gv.y, acc.y);
        }
    }

    atomicAdd(out + (size_t)r * WIDTH + 2 * lane,     acc.x);
    atomicAdd(out + (size_t)r * WIDTH + 2 * lane + 1, acc.y);
}

// ---------------------------------------------------------------------------
// Launch: zero -> h -> g -> msg (default stream, sequential deps)
// ---------------------------------------------------------------------------
extern "C" void kernel_launch(void* const* d_in, const int* in_sizes, int n_in,
                              void* d_out, int out_size) {
    const float* x   = (const float*)d_in[0];
    const float* ea  = (const float*)d_in[1];
    const float* W1  = (const float*)d_in[2];
    const float* b1  = (const float*)d_in[3];
    const float* W2  = (const float*)d_in[4];
    const float* b2  = (const float*)d_in[5];
    const int*   snd = (const int*)d_in[6];
    const int*   rcv = (const int*)d_in[7];
    float* out = (float*)d_out;

    k_zero<<<(NUM_NODES * WIDTH + 255) / 256, 256>>>(out, NUM_NODES * WIDTH);
    k_hidden<<<(NUM_EDGES * HIDDEN + 255) / 256, 256>>>(ea, W1, b1);

    dim3 gg((NUM_NODES + GT_N - 1) / GT_N, HIDDEN + 1);   // +1 = bias plane
    k_gmat<<<gg, 256>>>(x, W2, b2);

    k_msg<<<NUM_EDGES / 8, 256>>>(snd, rcv, out);
}

// round 7
// speedup vs baseline: 1.7367x; 1.7367x over previous
#include <cuda_runtime.h>
#include <cuda_bf16.h>
#include <cstdint>

// Problem constants (fixed by the dataset)
#define NUM_NODES 20000
#define NUM_EDGES 65536
#define WIDTH     64
#define EDGE_FEAT 6
#define HIDDEN    128

// Scratch (allocation-free rule: __device__ globals)
__device__ float g_h [(size_t)NUM_EDGES * HIDDEN];                 // 33.5 MB  relu(ea@W1+b1)
__device__ float g_g [(size_t)NUM_NODES * HIDDEN * WIDTH];         // 655 MB   g[n][k][v]
__device__ float g_xb[(size_t)NUM_NODES * WIDTH];                  // 5.1 MB   xb[n][v]
__device__ __nv_bfloat16 g_wt_hi[(size_t)HIDDEN * WIDTH * WIDTH];  // 2 MB  Wt[k][v][w] hi
__device__ __nv_bfloat16 g_wt_lo[(size_t)HIDDEN * WIDTH * WIDTH];  // 2 MB  Wt[k][v][w] lo

__device__ __forceinline__ void split_bf16(float a, unsigned short& hi, unsigned short& lo) {
    __nv_bfloat16 h = __float2bfloat16_rn(a);
    float r = a - __bfloat162float(h);
    __nv_bfloat16 l = __float2bfloat16_rn(r);
    hi = __bfloat16_as_ushort(h);
    lo = __bfloat16_as_ushort(l);
}

// Warp-level bf16 MMA (PTX sm_80 feature — compiles for plain sm_103 target,
// unlike tcgen05 which needs the sm_103a feature set this harness doesn't pass).
#define MMA_BF16(c, a, b0, b1) \
    asm volatile("mma.sync.aligned.m16n8k16.row.col.f32.bf16.bf16.f32 " \
        "{%0,%1,%2,%3}, {%4,%5,%6,%7}, {%8,%9}, {%0,%1,%2,%3};" \
        : "+f"((c)[0]), "+f"((c)[1]), "+f"((c)[2]), "+f"((c)[3]) \
        : "r"((a)[0]), "r"((a)[1]), "r"((a)[2]), "r"((a)[3]), "r"(b0), "r"(b1))

// ---------------------------------------------------------------------------
// Zero the output (harness poisons it with 0xAA)
// ---------------------------------------------------------------------------
__global__ void k_zero(float* __restrict__ out, int n) {
    int i = blockIdx.x * blockDim.x + threadIdx.x;
    if (i < n) out[i] = 0.f;
}

// ---------------------------------------------------------------------------
// h[e][k] = relu( sum_f edge_attr[e][f] * W1[f][k] + b1[k] )
// ---------------------------------------------------------------------------
__global__ void k_hidden(const float* __restrict__ ea,
                         const float* __restrict__ W1,
                         const float* __restrict__ b1) {
    int idx = blockIdx.x * blockDim.x + threadIdx.x;
    if (idx >= NUM_EDGES * HIDDEN) return;
    int e = idx >> 7;
    int j = idx & (HIDDEN - 1);
    const float* a = ea + (size_t)e * EDGE_FEAT;
    float s = __ldg(b1 + j);
    #pragma unroll
    for (int f = 0; f < EDGE_FEAT; f++)
        s = fmaf(__ldg(a + f), __ldg(W1 + f * HIDDEN + j), s);
    g_h[idx] = fmaxf(s, 0.f);
}

// ---------------------------------------------------------------------------
// Transpose+split W2 into Wt[k][v][w] = W2[k][w*64+v] as bf16 hi/lo (2 MB each)
// (Wt[k] is exactly the col-major B operand for mma.row.col: N=v rows, K=w contig)
// ---------------------------------------------------------------------------
__global__ void k_prep_w2(const float* __restrict__ W2) {
    int idx = blockIdx.x * blockDim.x + threadIdx.x;
    if (idx >= HIDDEN * WIDTH * WIDTH) return;
    int k = idx >> 12, rem = idx & 4095, v = rem >> 6, w = rem & 63;
    float val = W2[(size_t)k * 4096 + w * 64 + v];
    unsigned short hi, lo;
    split_bf16(val, hi, lo);
    g_wt_hi[idx] = __ushort_as_bfloat16(hi);
    g_wt_lo[idx] = __ushort_as_bfloat16(lo);
}

// ---------------------------------------------------------------------------
// xb[n][v] = sum_w x[n][w] * b2[w*64+v]   (fp32 SIMT, tiny)
// ---------------------------------------------------------------------------
__global__ __launch_bounds__(256) void k_xb(const float* __restrict__ x,
                                            const float* __restrict__ b2) {
    __shared__ float b2s[WIDTH * WIDTH];
    for (int i = threadIdx.x; i < WIDTH * WIDTH; i += 256) b2s[i] = b2[i];
    __syncthreads();
    int idx = blockIdx.x * 256 + threadIdx.x;
    if (idx >= NUM_NODES * WIDTH) return;
    int n = idx >> 6, v = idx & 63;
    const float* xr = x + (size_t)n * WIDTH;
    float s = 0.f;
    #pragma unroll
    for (int w = 0; w < WIDTH; w++) s = fmaf(xr[w], b2s[w * 64 + v], s);
    g_xb[idx] = s;
}

// ---------------------------------------------------------------------------
// HMMA g-GEMM: g[n][k][v] = sum_w x[n][w] * Wt[k][v][w]
// CTA = 128-node M-tile; 8 warps (4m x 2n), each a 32x32 C tile per k-plane.
// Split-bf16 (Ah*Bh + Ah*Bl + Al*Bh) => fp32-level accuracy.
// A fragments register-resident across all 128 planes; B register-prefetched.
// Smem rows padded to KP=72 bf16 -> conflict-free B fragment LDS.
// ---------------------------------------------------------------------------
#define KP 72
#define SMA_HI 0
#define SMA_LO (128 * KP * 2)                 // 18432
#define SMB_HI (2 * 128 * KP * 2)             // 36864
#define SMB_LO (SMB_HI + 64 * KP * 2)         // 46080
#define SM_TOT (SMB_LO + 64 * KP * 2)         // 55296 bytes

__global__ __launch_bounds__(256) void k_gmat_hmma(const float* __restrict__ x) {
    extern __shared__ char sm[];
    const int t    = threadIdx.x;
    const int lane = t & 31;
    const int warp = t >> 5;
    const int wm   = warp & 3;          // m-warp: rows wm*32..+31
    const int wn   = warp >> 2;         // n-warp: cols wn*32..+31
    const int n0   = blockIdx.x * 128;
    const int g    = lane >> 2;         // groupID 0..7
    const int l4   = lane & 3;

    // ---- Stage A tile: x rows -> bf16 hi/lo, padded KP-stride rows ----
    {
        const int row  = t >> 1;        // 0..127
        const int half = t & 1;         // which 32-float half of the row
        const int n    = n0 + row;
        float4 f4[8];
        if (n < NUM_NODES) {
            const float4* xr = (const float4*)(x + (size_t)n * WIDTH) + half * 8;
            #pragma unroll
            for (int j = 0; j < 8; j++) f4[j] = xr[j];
        } else {
            #pragma unroll
            for (int j = 0; j < 8; j++) f4[j] = make_float4(0.f, 0.f, 0.f, 0.f);
        }
        const float* f = (const float*)f4;
        #pragma unroll
        for (int c = 0; c < 4; c++) {   // 4 chunks of 8 bf16 (16B)
            uint32_t hw[4], lw[4];
            #pragma unroll
            for (int j = 0; j < 4; j++) {
                unsigned short h0, l0, h1, l1;
                split_bf16(f[c * 8 + j * 2 + 0], h0, l0);
                split_bf16(f[c * 8 + j * 2 + 1], h1, l1);
                hw[j] = (uint32_t)h0 | ((uint32_t)h1 << 16);
                lw[j] = (uint32_t)l0 | ((uint32_t)l1 << 16);
            }
            const uint32_t off = (uint32_t)row * (KP * 2) + half * 64 + c * 16;
            *(uint4*)(sm + SMA_HI + off) = make_uint4(hw[0], hw[1], hw[2], hw[3]);
            *(uint4*)(sm + SMA_LO + off) = make_uint4(lw[0], lw[1], lw[2], lw[3]);
        }
    }

    // ---- Stage B plane 0 into smem (padded) ----
    const uint4* wh4 = (const uint4*)g_wt_hi;
    const uint4* wl4 = (const uint4*)g_wt_lo;
    uint4 ph0 = wh4[t], ph1 = wh4[t + 256];
    uint4 pl0 = wl4[t], pl1 = wl4[t + 256];
    {
        const int i0 = t, i1 = t + 256;   // 16B chunks: v = i>>3, c = i&7
        *(uint4*)(sm + SMB_HI + (i0 >> 3) * (KP * 2) + (i0 & 7) * 16) = ph0;
        *(uint4*)(sm + SMB_HI + (i1 >> 3) * (KP * 2) + (i1 & 7) * 16) = ph1;
        *(uint4*)(sm + SMB_LO + (i0 >> 3) * (KP * 2) + (i0 & 7) * 16) = pl0;
        *(uint4*)(sm + SMB_LO + (i1 >> 3) * (KP * 2) + (i1 & 7) * 16) = pl1;
    }
    __syncthreads();

    // ---- Load A fragments once (reused for all 128 k-planes) ----
    // m16n8k16 A frag: a0={A[r][k0],A[r][k0+1]}, a1=row r+8, a2=cols+8, a3=both
    uint32_t Ah[2][4][4], Al[2][4][4];
    #pragma unroll
    for (int mt = 0; mt < 2; mt++) {
        #pragma unroll
        for (int kt = 0; kt < 4; kt++) {
            const int r0 = wm * 32 + mt * 16 + g;
            const int cb = kt * 16 + l4 * 2;
            Ah[mt][kt][0] = *(const uint32_t*)(sm + SMA_HI + ((size_t)r0 * KP + cb) * 2);
            Ah[mt][kt][1] = *(const uint32_t*)(sm + SMA_HI + ((size_t)(r0 + 8) * KP + cb) * 2);
            Ah[mt][kt][2] = *(const uint32_t*)(sm + SMA_HI + ((size_t)r0 * KP + cb + 8) * 2);
            Ah[mt][kt][3] = *(const uint32_t*)(sm + SMA_HI + ((size_t)(r0 + 8) * KP + cb + 8) * 2);
            Al[mt][kt][0] = *(const uint32_t*)(sm + SMA_LO + ((size_t)r0 * KP + cb) * 2);
            Al[mt][kt][1] = *(const uint32_t*)(sm + SMA_LO + ((size_t)(r0 + 8) * KP + cb) * 2);
            Al[mt][kt][2] = *(const uint32_t*)(sm + SMA_LO + ((size_t)r0 * KP + cb + 8) * 2);
            Al[mt][kt][3] = *(const uint32_t*)(sm + SMA_LO + ((size_t)(r0 + 8) * KP + cb + 8) * 2);
        }
    }

    // ---- Plane loop: compute 128x64 C per k, store, prefetch next B ----
    for (int k = 0; k < HIDDEN; k++) {
        if (k + 1 < HIDDEN) {            // register-prefetch next plane's B
            const size_t base = (size_t)(k + 1) * 512;
            ph0 = wh4[base + t];  ph1 = wh4[base + t + 256];
            pl0 = wl4[base + t];  pl1 = wl4[base + t + 256];
        }

        float C[2][4][4];
        #pragma unroll
        for (int mt = 0; mt < 2; mt++)
            #pragma unroll
            for (int nt = 0; nt < 4; nt++)
                #pragma unroll
                for (int i = 0; i < 4; i++) C[mt][nt][i] = 0.f;

        #pragma unroll
        for (int kt = 0; kt < 4; kt++) {
            #pragma unroll
            for (int nt = 0; nt < 4; nt++) {
                // m16n8k16 B frag from N x K storage: b0 at (n, k0), b1 at (n, k0+8)
                const uint32_t boff =
                    ((uint32_t)(wn * 32 + nt * 8 + g) * KP + kt * 16 + l4 * 2) * 2;
                const uint32_t bh0 = *(const uint32_t*)(sm + SMB_HI + boff);
                const uint32_t bh1 = *(const uint32_t*)(sm + SMB_HI + boff + 16);
                const uint32_t bl0 = *(const uint32_t*)(sm + SMB_LO + boff);
                const uint32_t bl1 = *(const uint32_t*)(sm + SMB_LO + boff + 16);
                #pragma unroll
                for (int mt = 0; mt < 2; mt++) {
                    MMA_BF16(C[mt][nt], Ah[mt][kt], bh0, bh1);
                    MMA_BF16(C[mt][nt], Ah[mt][kt], bl0, bl1);
                    MMA_BF16(C[mt][nt], Al[mt][kt], bh0, bh1);
                }
            }
        }

        // Store this k-plane: C frag c0,c1 @ (row, col..col+1); c2,c3 @ row+8
        #pragma unroll
        for (int mt = 0; mt < 2; mt++) {
            const int n1 = n0 + wm * 32 + mt * 16 + g;
            const int n2 = n1 + 8;
            #pragma unroll
            for (int nt = 0; nt < 4; nt++) {
                const int col = wn * 32 + nt * 8 + l4 * 2;
                if (n1 < NUM_NODES)
                    *(float2*)(g_g + ((size_t)n1 * HIDDEN + k) * WIDTH + col) =
                        make_float2(C[mt][nt][0], C[mt][nt][1]);
                if (n2 < NUM_NODES)
                    *(float2*)(g_g + ((size_t)n2 * HIDDEN + k) * WIDTH + col) =
                        make_float2(C[mt][nt][2], C[mt][nt][3]);
            }
        }

        __syncthreads();                 // all warps done reading B buffer
        if (k + 1 < HIDDEN) {
            const int i0 = t, i1 = t + 256;
            *(uint4*)(sm + SMB_HI + (i0 >> 3) * (KP * 2) + (i0 & 7) * 16) = ph0;
            *(uint4*)(sm + SMB_HI + (i1 >> 3) * (KP * 2) + (i1 & 7) * 16) = ph1;
            *(uint4*)(sm + SMB_LO + (i0 >> 3) * (KP * 2) + (i0 & 7) * 16) = pl0;
            *(uint4*)(sm + SMB_LO + (i1 >> 3) * (KP * 2) + (i1 & 7) * 16) = pl1;
            __syncthreads();             // B buffer ready for plane k+1
        }
    }
}

// ---------------------------------------------------------------------------
// Per edge e: msg[v] = sum_k h[e][k] * g[s][k][v] + xb[s][v];
// atomicAdd into out[r][v]. Warp per edge; relu-sparsity skips ~50% of gathers.
// ---------------------------------------------------------------------------
__global__ __launch_bounds__(256) void k_msg(const int* __restrict__ senders,
                                             const int* __restrict__ receivers,
                                             float* __restrict__ out) {
    __shared__ float hs[8][HIDDEN];
    const int wi   = threadIdx.x >> 5;
    const int lane = threadIdx.x & 31;
    const int e    = blockIdx.x * 8 + wi;
    if (e >= NUM_EDGES) return;

    #pragma unroll
    for (int j = 0; j < HIDDEN / 32; j++)
        hs[wi][j * 32 + lane] = g_h[(size_t)e * HIDDEN + j * 32 + lane];
    __syncwarp();

    const int s = senders[e];
    const int r = receivers[e];

    const float2* gp = (const float2*)(g_g + (size_t)s * HIDDEN * WIDTH) + lane;
    float2 acc = ((const float2*)(g_xb + (size_t)s * WIDTH))[lane];

    #pragma unroll 8
    for (int k = 0; k < HIDDEN; k++) {
        float hk = hs[wi][k];
        if (hk != 0.f) {
            float2 gv = gp[k * 32];
            acc.x = fmaf(hk, gv.x, acc.x);
            acc.y = fmaf(hk, gv.y, acc.y);
        }
    }

    atomicAdd(out + (size_t)r * WIDTH + 2 * lane,     acc.x);
    atomicAdd(out + (size_t)r * WIDTH + 2 * lane + 1, acc.y);
}

// ---------------------------------------------------------------------------
// Launch chain (default stream, sequential deps)
// ---------------------------------------------------------------------------
extern "C" void kernel_launch(void* const* d_in, const int* in_sizes, int n_in,
                              void* d_out, int out_size) {
    const float* x   = (const float*)d_in[0];
    const float* ea  = (const float*)d_in[1];
    const float* W1  = (const float*)d_in[2];
    const float* b1  = (const float*)d_in[3];
    const float* W2  = (const float*)d_in[4];
    const float* b2  = (const float*)d_in[5];
    const int*   snd = (const int*)d_in[6];
    const int*   rcv = (const int*)d_in[7];
    float* out = (float*)d_out;

    cudaFuncSetAttribute(k_gmat_hmma, cudaFuncAttributeMaxDynamicSharedMemorySize, SM_TOT);

    k_zero<<<(NUM_NODES * WIDTH + 255) / 256, 256>>>(out, NUM_NODES * WIDTH);
    k_hidden<<<(NUM_EDGES * HIDDEN + 255) / 256, 256>>>(ea, W1, b1);
    k_prep_w2<<<(HIDDEN * WIDTH * WIDTH + 255) / 256, 256>>>(W2);
    k_xb<<<(NUM_NODES * WIDTH + 255) / 256, 256>>>(x, b2);

    k_gmat_hmma<<<(NUM_NODES + 127) / 128, 256, SM_TOT>>>(x);

    k_msg<<<NUM_EDGES / 8, 256>>>(snd, rcv, out);
}